// round 12
// baseline (speedup 1.0000x reference)
#include <cuda_runtime.h>
#include <math.h>

#define BB   64
#define NN   256
#define HIDD 256
#define HH   4
#define CC   64
#define EE   8192
#define FIN  768
#define CHUNKS 32
#define CHSZ   256         // EE / CHUNKS
#define TWW    640         // per-warp scratch floats: 32 edges * stride 20
#define GWARPS 16          // warps per gat block

typedef unsigned long long ull;

// ---------------- scratch (no allocations allowed) ----------------
__device__ float g_H [(size_t)BB * NN * HIDD];
__device__ float g_H2[(size_t)BB * NN * HIDD];
__device__ float g_XL[(size_t)BB * NN * HIDD];
__device__ float g_XR[(size_t)BB * NN * HIDD];
__device__ float g_pool[BB * HIDD];
__device__ int   g_srcs[EE];
__device__ int   g_off[NN + 1];
__device__ int   g_cnt [CHUNKS][NN];
__device__ int   g_base[CHUNKS][NN];
__device__ int   g_rank[EE];

__device__ __forceinline__ float gelu_f(float x) {
    return 0.5f * x * (1.0f + erff(x * 0.70710678118654752f));
}

__device__ __forceinline__ unsigned f2t(float x) {
    unsigned u;
    asm("cvt.rna.tf32.f32 %0, %1;" : "=r"(u) : "f"(x));
    return u;
}

__device__ __forceinline__ void mma8(float& c0, float& c1, float& c2, float& c3,
                                     unsigned a0, unsigned a1, unsigned a2, unsigned a3,
                                     unsigned b0, unsigned b1) {
    asm volatile(
        "mma.sync.aligned.m16n8k8.row.col.f32.tf32.tf32.f32 "
        "{%0,%1,%2,%3},{%4,%5,%6,%7},{%8,%9},{%0,%1,%2,%3};"
        : "+f"(c0), "+f"(c1), "+f"(c2), "+f"(c3)
        : "r"(a0), "r"(a1), "r"(a2), "r"(a3), "r"(b0), "r"(b1));
}

// ---- packed f32x2 helpers (sm_103a) ----
__device__ __forceinline__ ull add2_(ull a, ull b) {
    ull d; asm("add.rn.f32x2 %0,%1,%2;" : "=l"(d) : "l"(a), "l"(b)); return d;
}
__device__ __forceinline__ ull mul2_(ull a, ull b) {
    ull d; asm("mul.rn.f32x2 %0,%1,%2;" : "=l"(d) : "l"(a), "l"(b)); return d;
}
__device__ __forceinline__ ull fma2_(ull a, ull b, ull c) {
    ull d; asm("fma.rn.f32x2 %0,%1,%2,%3;" : "=l"(d) : "l"(a), "l"(b), "l"(c)); return d;
}
__device__ __forceinline__ ull pk2(float x) {
    ull d; unsigned u = __float_as_uint(x);
    asm("mov.b64 %0,{%1,%1};" : "=l"(d) : "r"(u)); return d;
}
__device__ __forceinline__ ull pk2two(float x, float y) {
    ull d;
    asm("mov.b64 %0,{%1,%2};" : "=l"(d) : "r"(__float_as_uint(x)), "r"(__float_as_uint(y)));
    return d;
}
__device__ __forceinline__ float2 unpk(ull v) {
    unsigned lo, hi;
    asm("mov.b64 {%0,%1},%2;" : "=r"(lo), "=r"(hi) : "l"(v));
    return make_float2(__uint_as_float(lo), __uint_as_float(hi));
}

// ---------------- parallel deterministic counting sort, 3 phases ----------------
__global__ void sort_p1(const int* __restrict__ dst) {
    __shared__ int sd[CHSZ];
    const int ch = blockIdx.x, e = threadIdx.x;
    const int d = dst[ch * CHSZ + e];
    sd[e] = d;
    g_cnt[ch][e] = 0;
    __syncthreads();
    int rank = 0, tot = 0;
    #pragma unroll 8
    for (int j = 0; j < CHSZ; j++) {
        int v = sd[j];
        int m = (v == d);
        tot += m;
        rank += m & (j < e);
    }
    g_rank[ch * CHSZ + e] = rank;
    if (rank == 0) g_cnt[ch][d] = tot;
}

__global__ void sort_p2() {
    __shared__ int wsum[8];
    const int t = threadIdx.x;
    int run = 0;
    #pragma unroll
    for (int c = 0; c < CHUNKS; c++) {
        g_base[c][t] = run;
        run += g_cnt[c][t];
    }
    const int lane = t & 31, w = t >> 5;
    int inc = run;
    #pragma unroll
    for (int o = 1; o < 32; o <<= 1) {
        int n = __shfl_up_sync(0xffffffffu, inc, o);
        if (lane >= o) inc += n;
    }
    if (lane == 31) wsum[w] = inc;
    __syncthreads();
    if (t == 0) {
        int r = 0;
        #pragma unroll
        for (int i = 0; i < 8; i++) { int v = wsum[i]; wsum[i] = r; r += v; }
    }
    __syncthreads();
    const int offset = inc + wsum[w] - run;
    #pragma unroll
    for (int c = 0; c < CHUNKS; c++) g_base[c][t] += offset;
    g_off[t] = offset;
    if (t == NN - 1) g_off[NN] = EE;
}

__global__ void sort_p3(const int* __restrict__ src, const int* __restrict__ dst) {
    const int e = blockIdx.x * CHSZ + threadIdx.x;
    const int d = dst[e];
    g_srcs[g_base[blockIdx.x][d] + g_rank[e]] = src[e];
}

// ---------------- tf32 tensor-core GEMM: 128x128 CTA tile, BK=16 ----------------
#define ASTRIDE 20
#define BSTRIDE 136
template <int MODE>
__global__ void __launch_bounds__(256)
gemm_tc(const float* __restrict__ A,
        const float* __restrict__ B0, const float* __restrict__ B1,
        const float* __restrict__ bias0, const float* __restrict__ bias1,
        const float* __restrict__ gam, const float* __restrict__ bet,
        const float* __restrict__ rm, const float* __restrict__ rv,
        float* __restrict__ C0, float* __restrict__ C1,
        int M, int Nn, int K) {
    __shared__ unsigned As[2][128 * ASTRIDE];
    __shared__ unsigned Bs[2][16 * BSTRIDE];

    const float* Bm   = blockIdx.z ? B1 : B0;
    const float* bias = blockIdx.z ? bias1 : bias0;
    float* C          = blockIdx.z ? C1 : C0;

    const int tid = threadIdx.x;
    const int lane = tid & 31, wid = tid >> 5;
    const int gid = lane >> 2, tig = lane & 3;
    const int wm = wid & 1;
    const int wn = wid >> 1;
    const int bm = blockIdx.x * 128;
    const int bn = blockIdx.y * 128;

    const int ar0 = tid >> 2,         ac0 = (tid & 3) << 2;
    const int ar1 = (tid + 256) >> 2;
    const int bk0 = tid >> 5,         bc0 = (tid & 31) << 2;
    const int bk1 = (tid + 256) >> 5;

    const float* Ap0 = A + (size_t)(bm + ar0) * K + ac0;
    const float* Ap1 = A + (size_t)(bm + ar1) * K + ac0;
    const float* Bp0 = Bm + (size_t)bk0 * Nn + bn + bc0;
    const float* Bp1 = Bm + (size_t)bk1 * Nn + bn + bc0;

    float acc[4][4][4];
    #pragma unroll
    for (int i = 0; i < 4; i++)
        #pragma unroll
        for (int j = 0; j < 4; j++)
            #pragma unroll
            for (int q = 0; q < 4; q++) acc[i][j][q] = 0.f;

    float4 pa0 = *(const float4*)Ap0;
    float4 pa1 = *(const float4*)Ap1;
    float4 pb0 = *(const float4*)Bp0;
    float4 pb1 = *(const float4*)Bp1;

    {
        uint4 u;
        u.x = f2t(pa0.x); u.y = f2t(pa0.y); u.z = f2t(pa0.z); u.w = f2t(pa0.w);
        *(uint4*)&As[0][ar0 * ASTRIDE + ac0] = u;
        u.x = f2t(pa1.x); u.y = f2t(pa1.y); u.z = f2t(pa1.z); u.w = f2t(pa1.w);
        *(uint4*)&As[0][ar1 * ASTRIDE + ac0] = u;
        u.x = f2t(pb0.x); u.y = f2t(pb0.y); u.z = f2t(pb0.z); u.w = f2t(pb0.w);
        *(uint4*)&Bs[0][bk0 * BSTRIDE + bc0] = u;
        u.x = f2t(pb1.x); u.y = f2t(pb1.y); u.z = f2t(pb1.z); u.w = f2t(pb1.w);
        *(uint4*)&Bs[0][bk1 * BSTRIDE + bc0] = u;
    }
    __syncthreads();

    const int nsteps = K >> 4;
    int cur = 0;
    for (int kt = 0; kt < nsteps; kt++) {
        if (kt + 1 < nsteps) {
            pa0 = *(const float4*)(Ap0 + (kt + 1) * 16);
            pa1 = *(const float4*)(Ap1 + (kt + 1) * 16);
            pb0 = *(const float4*)(Bp0 + (size_t)(kt + 1) * 16 * Nn);
            pb1 = *(const float4*)(Bp1 + (size_t)(kt + 1) * 16 * Nn);
        }
        #pragma unroll
        for (int ks = 0; ks < 2; ks++) {
            const int k0 = ks * 8 + tig;
            unsigned af[4][4], bf[4][2];
            #pragma unroll
            for (int mt = 0; mt < 4; mt++) {
                int r = wm * 64 + mt * 16 + gid;
                af[mt][0] = As[cur][r * ASTRIDE + k0];
                af[mt][1] = As[cur][(r + 8) * ASTRIDE + k0];
                af[mt][2] = As[cur][r * ASTRIDE + k0 + 4];
                af[mt][3] = As[cur][(r + 8) * ASTRIDE + k0 + 4];
            }
            #pragma unroll
            for (int nt = 0; nt < 4; nt++) {
                int col = wn * 32 + nt * 8 + gid;
                bf[nt][0] = Bs[cur][k0 * BSTRIDE + col];
                bf[nt][1] = Bs[cur][(k0 + 4) * BSTRIDE + col];
            }
            #pragma unroll
            for (int mt = 0; mt < 4; mt++)
                #pragma unroll
                for (int nt = 0; nt < 4; nt++)
                    mma8(acc[mt][nt][0], acc[mt][nt][1], acc[mt][nt][2], acc[mt][nt][3],
                         af[mt][0], af[mt][1], af[mt][2], af[mt][3],
                         bf[nt][0], bf[nt][1]);
        }
        if (kt + 1 < nsteps) {
            int nxt = cur ^ 1;
            uint4 u;
            u.x = f2t(pa0.x); u.y = f2t(pa0.y); u.z = f2t(pa0.z); u.w = f2t(pa0.w);
            *(uint4*)&As[nxt][ar0 * ASTRIDE + ac0] = u;
            u.x = f2t(pa1.x); u.y = f2t(pa1.y); u.z = f2t(pa1.z); u.w = f2t(pa1.w);
            *(uint4*)&As[nxt][ar1 * ASTRIDE + ac0] = u;
            u.x = f2t(pb0.x); u.y = f2t(pb0.y); u.z = f2t(pb0.z); u.w = f2t(pb0.w);
            *(uint4*)&Bs[nxt][bk0 * BSTRIDE + bc0] = u;
            u.x = f2t(pb1.x); u.y = f2t(pb1.y); u.z = f2t(pb1.z); u.w = f2t(pb1.w);
            *(uint4*)&Bs[nxt][bk1 * BSTRIDE + bc0] = u;
            __syncthreads();
            cur = nxt;
        }
    }

    #pragma unroll
    for (int nt = 0; nt < 4; nt++) {
        int col = bn + wn * 32 + nt * 8 + 2 * tig;
        float bi0 = bias[col], bi1 = bias[col + 1];
        float g0 = 1.f, g1 = 1.f, b0 = 0.f, b1 = 0.f, m0 = 0.f, m1 = 0.f, s0 = 1.f, s1 = 1.f;
        if (MODE == 1) {
            g0 = gam[col]; g1 = gam[col + 1];
            b0 = bet[col]; b1 = bet[col + 1];
            m0 = rm[col];  m1 = rm[col + 1];
            s0 = rsqrtf(rv[col] + 1e-5f);
            s1 = rsqrtf(rv[col + 1] + 1e-5f);
        }
        #pragma unroll
        for (int mt = 0; mt < 4; mt++) {
            int row0 = bm + wm * 64 + mt * 16 + gid;
            float t0 = acc[mt][nt][0] + bi0;
            float t1 = acc[mt][nt][1] + bi1;
            float t2 = acc[mt][nt][2] + bi0;
            float t3 = acc[mt][nt][3] + bi1;
            if (MODE == 1) {
                t0 = gelu_f((t0 - m0) * s0 * g0 + b0);
                t1 = gelu_f((t1 - m1) * s1 * g1 + b1);
                t2 = gelu_f((t2 - m0) * s0 * g0 + b0);
                t3 = gelu_f((t3 - m1) * s1 * g1 + b1);
            }
            float2 o0 = {t0, t1};
            float2 o1 = {t2, t3};
            *(float2*)(C + (size_t)row0 * Nn + col) = o0;
            *(float2*)(C + (size_t)(row0 + 8) * Nn + col) = o1;
        }
    }
}

// ---------------- GATv2 v9: 16 warps/block (latency coverage), no max-sub ----------------
// block per (sample, head); warp per dst; lane = (p = lane>>4 edge parity,
// q = lane&15 channel quad). exp(l)/sum(exp(l)) == softmax (ratios identical).
__global__ void __launch_bounds__(512, 2)
gat_kernel(const float* __restrict__ XL, const float* __restrict__ XR,
           const float* __restrict__ att, const float* __restrict__ bo,
           float* __restrict__ OUT) {
    extern __shared__ float sm[];
    float* sxl = sm;                        // NN * 64       (64 KB)
    float* stw = sm + NN * 64;              // GWARPS * TWW  (40 KB)

    const int b = blockIdx.x, h = blockIdx.y;
    const int tid = threadIdx.x;
    const int w = tid >> 5, lane = tid & 31;
    const int p = lane >> 4, q = lane & 15;

    const float* xlb = XL + (size_t)b * NN * HIDD + h * CC;
    for (int i = tid; i < NN * 16; i += 512) {
        int n = i >> 4, g = i & 15;
        *(float4*)&sxl[n * 64 + g * 4] = *(const float4*)(xlb + (size_t)n * HIDD + g * 4);
    }
    __syncthreads();

    // leaky(t) = 0.6t + 0.4|t| for slope 0.2
    const float4 av = *(const float4*)(att + h * CC + 4 * q);
    const ull c6a = pk2two(0.6f * av.x, 0.6f * av.y);
    const ull c6b = pk2two(0.6f * av.z, 0.6f * av.w);
    const ull c4a = pk2two(0.4f * av.x, 0.4f * av.y);
    const ull c4b = pk2two(0.4f * av.z, 0.4f * av.w);
    const float4 bo4 = *(const float4*)(bo + h * CC + 4 * q);
    const ull ABSM = 0x7fffffff7fffffffULL;

    float* tw = stw + w * TWW;
    const int* __restrict__ srcs = g_srcs;
    const float* xr_base = XR + (size_t)b * NN * HIDD + h * CC + 4 * q;

    for (int d = w; d < NN; d += GWARPS) {
        const int e0 = g_off[d], e1 = g_off[d + 1];
        const float4 xr4 = *(const float4*)(xr_base + (size_t)d * HIDD);
        const ull xra = pk2two(xr4.x, xr4.y);
        const ull xrb = pk2two(xr4.z, xr4.w);

        float S = 0.f;
        ull acc0 = 0ull, acc1 = 0ull;

        for (int base = e0; base < e1; base += 32) {
            const int n = min(32, e1 - base);
            const int sr = srcs[min(base + lane, EE - 1)];

            __syncwarp();
            // pass A: one LDS.128 serves TWO edges; per-lane 4-ch partial -> scratch
            #pragma unroll
            for (int k = 0; k < 16; k++) {
                int s = __shfl_sync(0xffffffffu, sr, 2 * k + p);
                ulonglong2 rv = *(const ulonglong2*)(sxl + (s << 6) + 4 * q);
                ull t0 = add2_(rv.x, xra);
                ull t1 = add2_(rv.y, xrb);
                ull m = fma2_(t0 & ABSM, c4a, mul2_(t0, c6a));
                m = fma2_(t1 & ABSM, c4b, fma2_(t1, c6b, m));
                float2 pr = unpk(m);
                tw[(2 * k + p) * 20 + q] = pr.x + pr.y;
            }
            __syncwarp();

            // lane j: sum edge j's 16 partials, exp directly (no max-sub)
            float wgt = 0.f;
            {
                const float4* r4 = (const float4*)(tw + lane * 20);
                float4 q0 = r4[0], q1 = r4[1], q2 = r4[2], q3 = r4[3];
                float s0 = ((q0.x + q0.y) + (q0.z + q0.w)) + ((q1.x + q1.y) + (q1.z + q1.w));
                float s1 = ((q2.x + q2.y) + (q2.z + q2.w)) + ((q3.x + q3.y) + (q3.z + q3.w));
                if (lane < n) wgt = __expf(s0 + s1);
            }
            float ss = wgt;
            #pragma unroll
            for (int o = 16; o > 0; o >>= 1) ss += __shfl_xor_sync(0xffffffffu, ss, o);
            S += ss;

            // pass B: re-read rows (frees registers), weight via shfl broadcast
            #pragma unroll
            for (int k = 0; k < 16; k++) {
                int s = __shfl_sync(0xffffffffu, sr, 2 * k + p);
                float wj = __shfl_sync(0xffffffffu, wgt, 2 * k + p);
                ulonglong2 rv = *(const ulonglong2*)(sxl + (s << 6) + 4 * q);
                ull wv = pk2(wj);
                acc0 = fma2_(rv.x, wv, acc0);
                acc1 = fma2_(rv.y, wv, acc1);
            }
        }

        // combine p=0 / p=1 halves (same q, lane ^ 16)
        float2 a0 = unpk(acc0), a1 = unpk(acc1);
        a0.x += __shfl_xor_sync(0xffffffffu, a0.x, 16);
        a0.y += __shfl_xor_sync(0xffffffffu, a0.y, 16);
        a1.x += __shfl_xor_sync(0xffffffffu, a1.x, 16);
        a1.y += __shfl_xor_sync(0xffffffffu, a1.y, 16);

        const float inv = 1.f / (S + 1e-16f);
        float4 ov;
        ov.x = gelu_f(fmaf(a0.x, inv, bo4.x));
        ov.y = gelu_f(fmaf(a0.y, inv, bo4.y));
        ov.z = gelu_f(fmaf(a1.x, inv, bo4.z));
        ov.w = gelu_f(fmaf(a1.y, inv, bo4.w));
        if (p == 0)
            *(float4*)(OUT + ((size_t)b * NN + d) * HIDD + h * CC + 4 * q) = ov;
    }
}

// ---------------- mean-pool over nodes ----------------
__global__ void pool_kernel(const float* __restrict__ H, float* __restrict__ P) {
    int b = blockIdx.x, f = threadIdx.x;
    float s = 0.f;
    #pragma unroll 4
    for (int n = 0; n < NN; n++) s += H[((size_t)b * NN + n) * HIDD + f];
    P[b * HIDD + f] = s * (1.0f / NN);
}

// ---------------- tiny output GEMM + BN + GELU ----------------
__global__ void gemm2_kernel(const float* __restrict__ P, const float* __restrict__ W,
                             const float* __restrict__ bias,
                             const float* __restrict__ gam, const float* __restrict__ bet,
                             const float* __restrict__ rm, const float* __restrict__ rv,
                             float* __restrict__ out) {
    __shared__ float sp[HIDD];
    int b = blockIdx.x, j = threadIdx.x;
    sp[j] = P[b * HIDD + j];
    __syncthreads();
    float acc = 0.f;
    #pragma unroll 4
    for (int k = 0; k < HIDD; k++) acc = fmaf(sp[k], W[(size_t)k * HIDD + j], acc);
    float t = acc + bias[j];
    t = (t - rm[j]) * rsqrtf(rv[j] + 1e-5f) * gam[j] + bet[j];
    out[b * HIDD + j] = gelu_f(t);
}

#define GAT_SMEM ((NN * 64 + GWARPS * TWW) * (int)sizeof(float))

extern "C" void kernel_launch(void* const* d_in, const int* in_sizes, int n_in,
                              void* d_out, int out_size) {
    const float* x    = (const float*)d_in[0];
    const int*   ei   = (const int*)d_in[1];
    const float* W1   = (const float*)d_in[2];
    const float* b1   = (const float*)d_in[3];
    const float* g1   = (const float*)d_in[4];
    const float* be1  = (const float*)d_in[5];
    const float* m1   = (const float*)d_in[6];
    const float* v1   = (const float*)d_in[7];
    const float* Wl0  = (const float*)d_in[8];
    const float* bl0  = (const float*)d_in[9];
    const float* Wr0  = (const float*)d_in[10];
    const float* br0  = (const float*)d_in[11];
    const float* att0 = (const float*)d_in[12];
    const float* bo0  = (const float*)d_in[13];
    const float* Wl1  = (const float*)d_in[14];
    const float* bl1  = (const float*)d_in[15];
    const float* Wr1  = (const float*)d_in[16];
    const float* br1  = (const float*)d_in[17];
    const float* att1 = (const float*)d_in[18];
    const float* bo1  = (const float*)d_in[19];
    const float* W2   = (const float*)d_in[20];
    const float* b2   = (const float*)d_in[21];
    const float* g2   = (const float*)d_in[22];
    const float* be2  = (const float*)d_in[23];
    const float* m2   = (const float*)d_in[24];
    const float* v2   = (const float*)d_in[25];
    float* out = (float*)d_out;

    float *H, *H2, *XL, *XR, *P;
    cudaGetSymbolAddress((void**)&H,  g_H);
    cudaGetSymbolAddress((void**)&H2, g_H2);
    cudaGetSymbolAddress((void**)&XL, g_XL);
    cudaGetSymbolAddress((void**)&XR, g_XR);
    cudaGetSymbolAddress((void**)&P,  g_pool);

    cudaFuncSetAttribute(gat_kernel, cudaFuncAttributeMaxDynamicSharedMemorySize, GAT_SMEM);

    const int M = BB * NN;  // 16384
    const int* src = ei;
    const int* dst = ei + EE;

    sort_p1<<<CHUNKS, CHSZ>>>(dst);
    sort_p2<<<1, 256>>>();
    sort_p3<<<CHUNKS, CHSZ>>>(src, dst);

    // node_proj
    gemm_tc<1><<<dim3(M / 128, HIDD / 128, 1), 256>>>(
        x, W1, W1, b1, b1, g1, be1, m1, v1, H, H, M, HIDD, FIN);

    // layer 0: XL and XR in one launch (grid.z selects)
    gemm_tc<0><<<dim3(M / 128, HIDD / 128, 2), 256>>>(
        H, Wl0, Wr0, bl0, br0, 0, 0, 0, 0, XL, XR, M, HIDD, HIDD);
    gat_kernel<<<dim3(BB, HH), 512, GAT_SMEM>>>(XL, XR, att0, bo0, H2);

    // layer 1
    gemm_tc<0><<<dim3(M / 128, HIDD / 128, 2), 256>>>(
        H2, Wl1, Wr1, bl1, br1, 0, 0, 0, 0, XL, XR, M, HIDD, HIDD);
    gat_kernel<<<dim3(BB, HH), 512, GAT_SMEM>>>(XL, XR, att1, bo1, H);

    // pool + output proj
    pool_kernel<<<BB, HIDD>>>(H, P);
    gemm2_kernel<<<BB, HIDD>>>(P, W2, b2, g2, be2, m2, v2, out);
}

// round 13
// speedup vs baseline: 1.0774x; 1.0774x over previous
#include <cuda_runtime.h>
#include <math.h>

#define BB   64
#define NN   256
#define HIDD 256
#define HH   4
#define CC   64
#define EE   8192
#define FIN  768
#define CHUNKS 32
#define CHSZ   256         // EE / CHUNKS
#define TWW    640         // per-warp scratch floats: 32 edges * stride 20

typedef unsigned long long ull;

// ---------------- scratch (no allocations allowed) ----------------
__device__ float g_H [(size_t)BB * NN * HIDD];
__device__ float g_H2[(size_t)BB * NN * HIDD];
__device__ float g_XL[(size_t)BB * NN * HIDD];
__device__ float g_XR[(size_t)BB * NN * HIDD];
__device__ float g_pool[BB * HIDD];
__device__ int   g_srcs[EE];
__device__ int   g_off[NN + 1];
__device__ int   g_cnt [CHUNKS][NN];
__device__ int   g_base[CHUNKS][NN];
__device__ int   g_rank[EE];

__device__ __forceinline__ float gelu_f(float x) {
    return 0.5f * x * (1.0f + erff(x * 0.70710678118654752f));
}

__device__ __forceinline__ unsigned f2t(float x) {
    unsigned u;
    asm("cvt.rna.tf32.f32 %0, %1;" : "=r"(u) : "f"(x));
    return u;
}

__device__ __forceinline__ void mma8(float& c0, float& c1, float& c2, float& c3,
                                     unsigned a0, unsigned a1, unsigned a2, unsigned a3,
                                     unsigned b0, unsigned b1) {
    asm volatile(
        "mma.sync.aligned.m16n8k8.row.col.f32.tf32.tf32.f32 "
        "{%0,%1,%2,%3},{%4,%5,%6,%7},{%8,%9},{%0,%1,%2,%3};"
        : "+f"(c0), "+f"(c1), "+f"(c2), "+f"(c3)
        : "r"(a0), "r"(a1), "r"(a2), "r"(a3), "r"(b0), "r"(b1));
}

// ---- packed f32x2 helpers (sm_103a) ----
__device__ __forceinline__ ull add2_(ull a, ull b) {
    ull d; asm("add.rn.f32x2 %0,%1,%2;" : "=l"(d) : "l"(a), "l"(b)); return d;
}
__device__ __forceinline__ ull mul2_(ull a, ull b) {
    ull d; asm("mul.rn.f32x2 %0,%1,%2;" : "=l"(d) : "l"(a), "l"(b)); return d;
}
__device__ __forceinline__ ull fma2_(ull a, ull b, ull c) {
    ull d; asm("fma.rn.f32x2 %0,%1,%2,%3;" : "=l"(d) : "l"(a), "l"(b), "l"(c)); return d;
}
__device__ __forceinline__ ull pk2(float x) {
    ull d; unsigned u = __float_as_uint(x);
    asm("mov.b64 %0,{%1,%1};" : "=l"(d) : "r"(u)); return d;
}
__device__ __forceinline__ ull pk2two(float x, float y) {
    ull d;
    asm("mov.b64 %0,{%1,%2};" : "=l"(d) : "r"(__float_as_uint(x)), "r"(__float_as_uint(y)));
    return d;
}
__device__ __forceinline__ float2 unpk(ull v) {
    unsigned lo, hi;
    asm("mov.b64 {%0,%1},%2;" : "=r"(lo), "=r"(hi) : "l"(v));
    return make_float2(__uint_as_float(lo), __uint_as_float(hi));
}

// compiler-only memory fence: per-warp MIO is in-order, so cross-lane
// STS->LDS within a non-divergent warp needs only a compile barrier.
#define CFENCE() asm volatile("" ::: "memory")

// ---------------- parallel deterministic counting sort, 3 phases ----------------
__global__ void sort_p1(const int* __restrict__ dst) {
    __shared__ int sd[CHSZ];
    const int ch = blockIdx.x, e = threadIdx.x;
    const int d = dst[ch * CHSZ + e];
    sd[e] = d;
    g_cnt[ch][e] = 0;
    __syncthreads();
    int rank = 0, tot = 0;
    #pragma unroll 8
    for (int j = 0; j < CHSZ; j++) {
        int v = sd[j];
        int m = (v == d);
        tot += m;
        rank += m & (j < e);
    }
    g_rank[ch * CHSZ + e] = rank;
    if (rank == 0) g_cnt[ch][d] = tot;
}

__global__ void sort_p2() {
    __shared__ int wsum[8];
    const int t = threadIdx.x;
    int run = 0;
    #pragma unroll
    for (int c = 0; c < CHUNKS; c++) {
        g_base[c][t] = run;
        run += g_cnt[c][t];
    }
    const int lane = t & 31, w = t >> 5;
    int inc = run;
    #pragma unroll
    for (int o = 1; o < 32; o <<= 1) {
        int n = __shfl_up_sync(0xffffffffu, inc, o);
        if (lane >= o) inc += n;
    }
    if (lane == 31) wsum[w] = inc;
    __syncthreads();
    if (t == 0) {
        int r = 0;
        #pragma unroll
        for (int i = 0; i < 8; i++) { int v = wsum[i]; wsum[i] = r; r += v; }
    }
    __syncthreads();
    const int offset = inc + wsum[w] - run;
    #pragma unroll
    for (int c = 0; c < CHUNKS; c++) g_base[c][t] += offset;
    g_off[t] = offset;
    if (t == NN - 1) g_off[NN] = EE;
}

__global__ void sort_p3(const int* __restrict__ src, const int* __restrict__ dst) {
    const int e = blockIdx.x * CHSZ + threadIdx.x;
    const int d = dst[e];
    g_srcs[g_base[blockIdx.x][d] + g_rank[e]] = src[e];
}

// ---------------- tf32 tensor-core GEMM: 128x128 CTA tile, BK=16 ----------------
#define ASTRIDE 20
#define BSTRIDE 136
template <int MODE>
__global__ void __launch_bounds__(256)
gemm_tc(const float* __restrict__ A,
        const float* __restrict__ B0, const float* __restrict__ B1,
        const float* __restrict__ bias0, const float* __restrict__ bias1,
        const float* __restrict__ gam, const float* __restrict__ bet,
        const float* __restrict__ rm, const float* __restrict__ rv,
        float* __restrict__ C0, float* __restrict__ C1,
        int M, int Nn, int K) {
    __shared__ unsigned As[2][128 * ASTRIDE];
    __shared__ unsigned Bs[2][16 * BSTRIDE];

    const float* Bm   = blockIdx.z ? B1 : B0;
    const float* bias = blockIdx.z ? bias1 : bias0;
    float* C          = blockIdx.z ? C1 : C0;

    const int tid = threadIdx.x;
    const int lane = tid & 31, wid = tid >> 5;
    const int gid = lane >> 2, tig = lane & 3;
    const int wm = wid & 1;
    const int wn = wid >> 1;
    const int bm = blockIdx.x * 128;
    const int bn = blockIdx.y * 128;

    const int ar0 = tid >> 2,         ac0 = (tid & 3) << 2;
    const int ar1 = (tid + 256) >> 2;
    const int bk0 = tid >> 5,         bc0 = (tid & 31) << 2;
    const int bk1 = (tid + 256) >> 5;

    const float* Ap0 = A + (size_t)(bm + ar0) * K + ac0;
    const float* Ap1 = A + (size_t)(bm + ar1) * K + ac0;
    const float* Bp0 = Bm + (size_t)bk0 * Nn + bn + bc0;
    const float* Bp1 = Bm + (size_t)bk1 * Nn + bn + bc0;

    float acc[4][4][4];
    #pragma unroll
    for (int i = 0; i < 4; i++)
        #pragma unroll
        for (int j = 0; j < 4; j++)
            #pragma unroll
            for (int q = 0; q < 4; q++) acc[i][j][q] = 0.f;

    float4 pa0 = *(const float4*)Ap0;
    float4 pa1 = *(const float4*)Ap1;
    float4 pb0 = *(const float4*)Bp0;
    float4 pb1 = *(const float4*)Bp1;

    {
        uint4 u;
        u.x = f2t(pa0.x); u.y = f2t(pa0.y); u.z = f2t(pa0.z); u.w = f2t(pa0.w);
        *(uint4*)&As[0][ar0 * ASTRIDE + ac0] = u;
        u.x = f2t(pa1.x); u.y = f2t(pa1.y); u.z = f2t(pa1.z); u.w = f2t(pa1.w);
        *(uint4*)&As[0][ar1 * ASTRIDE + ac0] = u;
        u.x = f2t(pb0.x); u.y = f2t(pb0.y); u.z = f2t(pb0.z); u.w = f2t(pb0.w);
        *(uint4*)&Bs[0][bk0 * BSTRIDE + bc0] = u;
        u.x = f2t(pb1.x); u.y = f2t(pb1.y); u.z = f2t(pb1.z); u.w = f2t(pb1.w);
        *(uint4*)&Bs[0][bk1 * BSTRIDE + bc0] = u;
    }
    __syncthreads();

    const int nsteps = K >> 4;
    int cur = 0;
    for (int kt = 0; kt < nsteps; kt++) {
        if (kt + 1 < nsteps) {
            pa0 = *(const float4*)(Ap0 + (kt + 1) * 16);
            pa1 = *(const float4*)(Ap1 + (kt + 1) * 16);
            pb0 = *(const float4*)(Bp0 + (size_t)(kt + 1) * 16 * Nn);
            pb1 = *(const float4*)(Bp1 + (size_t)(kt + 1) * 16 * Nn);
        }
        #pragma unroll
        for (int ks = 0; ks < 2; ks++) {
            const int k0 = ks * 8 + tig;
            unsigned af[4][4], bf[4][2];
            #pragma unroll
            for (int mt = 0; mt < 4; mt++) {
                int r = wm * 64 + mt * 16 + gid;
                af[mt][0] = As[cur][r * ASTRIDE + k0];
                af[mt][1] = As[cur][(r + 8) * ASTRIDE + k0];
                af[mt][2] = As[cur][r * ASTRIDE + k0 + 4];
                af[mt][3] = As[cur][(r + 8) * ASTRIDE + k0 + 4];
            }
            #pragma unroll
            for (int nt = 0; nt < 4; nt++) {
                int col = wn * 32 + nt * 8 + gid;
                bf[nt][0] = Bs[cur][k0 * BSTRIDE + col];
                bf[nt][1] = Bs[cur][(k0 + 4) * BSTRIDE + col];
            }
            #pragma unroll
            for (int mt = 0; mt < 4; mt++)
                #pragma unroll
                for (int nt = 0; nt < 4; nt++)
                    mma8(acc[mt][nt][0], acc[mt][nt][1], acc[mt][nt][2], acc[mt][nt][3],
                         af[mt][0], af[mt][1], af[mt][2], af[mt][3],
                         bf[nt][0], bf[nt][1]);
        }
        if (kt + 1 < nsteps) {
            int nxt = cur ^ 1;
            uint4 u;
            u.x = f2t(pa0.x); u.y = f2t(pa0.y); u.z = f2t(pa0.z); u.w = f2t(pa0.w);
            *(uint4*)&As[nxt][ar0 * ASTRIDE + ac0] = u;
            u.x = f2t(pa1.x); u.y = f2t(pa1.y); u.z = f2t(pa1.z); u.w = f2t(pa1.w);
            *(uint4*)&As[nxt][ar1 * ASTRIDE + ac0] = u;
            u.x = f2t(pb0.x); u.y = f2t(pb0.y); u.z = f2t(pb0.z); u.w = f2t(pb0.w);
            *(uint4*)&Bs[nxt][bk0 * BSTRIDE + bc0] = u;
            u.x = f2t(pb1.x); u.y = f2t(pb1.y); u.z = f2t(pb1.z); u.w = f2t(pb1.w);
            *(uint4*)&Bs[nxt][bk1 * BSTRIDE + bc0] = u;
            __syncthreads();
            cur = nxt;
        }
    }

    #pragma unroll
    for (int nt = 0; nt < 4; nt++) {
        int col = bn + wn * 32 + nt * 8 + 2 * tig;
        float bi0 = bias[col], bi1 = bias[col + 1];
        float g0 = 1.f, g1 = 1.f, b0 = 0.f, b1 = 0.f, m0 = 0.f, m1 = 0.f, s0 = 1.f, s1 = 1.f;
        if (MODE == 1) {
            g0 = gam[col]; g1 = gam[col + 1];
            b0 = bet[col]; b1 = bet[col + 1];
            m0 = rm[col];  m1 = rm[col + 1];
            s0 = rsqrtf(rv[col] + 1e-5f);
            s1 = rsqrtf(rv[col + 1] + 1e-5f);
        }
        #pragma unroll
        for (int mt = 0; mt < 4; mt++) {
            int row0 = bm + wm * 64 + mt * 16 + gid;
            float t0 = acc[mt][nt][0] + bi0;
            float t1 = acc[mt][nt][1] + bi1;
            float t2 = acc[mt][nt][2] + bi0;
            float t3 = acc[mt][nt][3] + bi1;
            if (MODE == 1) {
                t0 = gelu_f((t0 - m0) * s0 * g0 + b0);
                t1 = gelu_f((t1 - m1) * s1 * g1 + b1);
                t2 = gelu_f((t2 - m0) * s0 * g0 + b0);
                t3 = gelu_f((t3 - m1) * s1 * g1 + b1);
            }
            float2 o0 = {t0, t1};
            float2 o1 = {t2, t3};
            *(float2*)(C + (size_t)row0 * Nn + col) = o0;
            *(float2*)(C + (size_t)(row0 + 8) * Nn + col) = o1;
        }
    }
}

// ---------------- GATv2 v10: v6 minus syncwarps and max-subtraction ----------------
// block per (sample, head); warp per dst; lane = (p = lane>>4 edge parity,
// q = lane&15 channel quad). One LDS.128 serves TWO edges.
// weights = exp(logit) directly (ratio-identical to softmax; logits O(+-5)).
__global__ void __launch_bounds__(256, 2)
gat_kernel(const float* __restrict__ XL, const float* __restrict__ XR,
           const float* __restrict__ att, const float* __restrict__ bo,
           float* __restrict__ OUT) {
    extern __shared__ float sm[];
    float* sxl = sm;                        // NN * 64  (64 KB)
    float* stw = sm + NN * 64;              // 8 * TWW  (20 KB)

    const int b = blockIdx.x, h = blockIdx.y;
    const int tid = threadIdx.x;
    const int w = tid >> 5, lane = tid & 31;
    const int p = lane >> 4, q = lane & 15;

    // fill sxl (rows of exactly 64 floats; float4, conflict-free)
    const float* xlb = XL + (size_t)b * NN * HIDD + h * CC;
    for (int i = tid; i < NN * 16; i += 256) {
        int n = i >> 4, g = i & 15;
        *(float4*)&sxl[n * 64 + g * 4] = *(const float4*)(xlb + (size_t)n * HIDD + g * 4);
    }
    __syncthreads();

    // lane's 4 attention coeffs (leaky(t) = 0.6t + 0.4|t| for slope 0.2)
    const float4 av = *(const float4*)(att + h * CC + 4 * q);
    const ull c6a = pk2two(0.6f * av.x, 0.6f * av.y);
    const ull c6b = pk2two(0.6f * av.z, 0.6f * av.w);
    const ull c4a = pk2two(0.4f * av.x, 0.4f * av.y);
    const ull c4b = pk2two(0.4f * av.z, 0.4f * av.w);
    const float4 bo4 = *(const float4*)(bo + h * CC + 4 * q);
    const ull ABSM = 0x7fffffff7fffffffULL;

    float* tw = stw + w * TWW;
    const int* __restrict__ srcs = g_srcs;
    const float* xr_base = XR + (size_t)b * NN * HIDD + h * CC + 4 * q;

    for (int d = w; d < NN; d += 8) {
        const int e0 = g_off[d], e1 = g_off[d + 1];
        const float4 xr4 = *(const float4*)(xr_base + (size_t)d * HIDD);
        const ull xra = pk2two(xr4.x, xr4.y);
        const ull xrb = pk2two(xr4.z, xr4.w);

        float S = 0.f;
        ull acc0 = 0ull, acc1 = 0ull;

        for (int base = e0; base < e1; base += 32) {
            const int n = min(32, e1 - base);
            const int sreg = srcs[min(base + lane, EE - 1)];
            ulonglong2 vreg[16];

            CFENCE();   // WAR: previous chunk's tw reads before this chunk's writes
            // pass A: one LDS.128 per TWO edges; per-lane 4-ch partial -> scratch
            #pragma unroll
            for (int k = 0; k < 16; k++) {
                int s = __shfl_sync(0xffffffffu, sreg, 2 * k + p);
                ulonglong2 rv = *(const ulonglong2*)(sxl + (s << 6) + 4 * q);
                vreg[k] = rv;
                ull t0 = add2_(rv.x, xra);
                ull t1 = add2_(rv.y, xrb);
                ull m = fma2_(t0 & ABSM, c4a, mul2_(t0, c6a));
                m = fma2_(t1 & ABSM, c4b, fma2_(t1, c6b, m));
                float2 pr = unpk(m);
                tw[(2 * k + p) * 20 + q] = pr.x + pr.y;     // STS.32, <=2-way
            }
            CFENCE();   // RAW: per-warp MIO is in-order; only compiler fence needed

            // lane j sums edge j's 16 partials (4x LDS.128), exp directly
            float wgt = 0.f;
            {
                const float4* r4 = (const float4*)(tw + lane * 20);
                float4 q0 = r4[0], q1 = r4[1], q2 = r4[2], q3 = r4[3];
                float s0 = ((q0.x + q0.y) + (q0.z + q0.w)) + ((q1.x + q1.y) + (q1.z + q1.w));
                float s1 = ((q2.x + q2.y) + (q2.z + q2.w)) + ((q3.x + q3.y) + (q3.z + q3.w));
                if (lane < n) wgt = __expf(s0 + s1);
            }
            float ss = wgt;
            #pragma unroll
            for (int o = 16; o > 0; o >>= 1) ss += __shfl_xor_sync(0xffffffffu, ss, o);
            S += ss;

            // pass B: accumulate from register-cached rows, weight via shfl
            #pragma unroll
            for (int k = 0; k < 16; k++) {
                float wj = __shfl_sync(0xffffffffu, wgt, 2 * k + p);
                ull wv = pk2(wj);
                acc0 = fma2_(vreg[k].x, wv, acc0);
                acc1 = fma2_(vreg[k].y, wv, acc1);
            }
        }

        // combine p=0 / p=1 halves (same q, lane ^ 16)
        float2 a0 = unpk(acc0), a1 = unpk(acc1);
        a0.x += __shfl_xor_sync(0xffffffffu, a0.x, 16);
        a0.y += __shfl_xor_sync(0xffffffffu, a0.y, 16);
        a1.x += __shfl_xor_sync(0xffffffffu, a1.x, 16);
        a1.y += __shfl_xor_sync(0xffffffffu, a1.y, 16);

        const float inv = 1.f / (S + 1e-16f);
        float4 ov;
        ov.x = gelu_f(fmaf(a0.x, inv, bo4.x));
        ov.y = gelu_f(fmaf(a0.y, inv, bo4.y));
        ov.z = gelu_f(fmaf(a1.x, inv, bo4.z));
        ov.w = gelu_f(fmaf(a1.y, inv, bo4.w));
        if (p == 0)
            *(float4*)(OUT + ((size_t)b * NN + d) * HIDD + h * CC + 4 * q) = ov;
    }
}

// ---------------- mean-pool over nodes ----------------
__global__ void pool_kernel(const float* __restrict__ H, float* __restrict__ P) {
    int b = blockIdx.x, f = threadIdx.x;
    float s = 0.f;
    #pragma unroll 4
    for (int n = 0; n < NN; n++) s += H[((size_t)b * NN + n) * HIDD + f];
    P[b * HIDD + f] = s * (1.0f / NN);
}

// ---------------- tiny output GEMM + BN + GELU ----------------
__global__ void gemm2_kernel(const float* __restrict__ P, const float* __restrict__ W,
                             const float* __restrict__ bias,
                             const float* __restrict__ gam, const float* __restrict__ bet,
                             const float* __restrict__ rm, const float* __restrict__ rv,
                             float* __restrict__ out) {
    __shared__ float sp[HIDD];
    int b = blockIdx.x, j = threadIdx.x;
    sp[j] = P[b * HIDD + j];
    __syncthreads();
    float acc = 0.f;
    #pragma unroll 4
    for (int k = 0; k < HIDD; k++) acc = fmaf(sp[k], W[(size_t)k * HIDD + j], acc);
    float t = acc + bias[j];
    t = (t - rm[j]) * rsqrtf(rv[j] + 1e-5f) * gam[j] + bet[j];
    out[b * HIDD + j] = gelu_f(t);
}

#define GAT_SMEM ((NN * 64 + 8 * TWW) * (int)sizeof(float))

extern "C" void kernel_launch(void* const* d_in, const int* in_sizes, int n_in,
                              void* d_out, int out_size) {
    const float* x    = (const float*)d_in[0];
    const int*   ei   = (const int*)d_in[1];
    const float* W1   = (const float*)d_in[2];
    const float* b1   = (const float*)d_in[3];
    const float* g1   = (const float*)d_in[4];
    const float* be1  = (const float*)d_in[5];
    const float* m1   = (const float*)d_in[6];
    const float* v1   = (const float*)d_in[7];
    const float* Wl0  = (const float*)d_in[8];
    const float* bl0  = (const float*)d_in[9];
    const float* Wr0  = (const float*)d_in[10];
    const float* br0  = (const float*)d_in[11];
    const float* att0 = (const float*)d_in[12];
    const float* bo0  = (const float*)d_in[13];
    const float* Wl1  = (const float*)d_in[14];
    const float* bl1  = (const float*)d_in[15];
    const float* Wr1  = (const float*)d_in[16];
    const float* br1  = (const float*)d_in[17];
    const float* att1 = (const float*)d_in[18];
    const float* bo1  = (const float*)d_in[19];
    const float* W2   = (const float*)d_in[20];
    const float* b2   = (const float*)d_in[21];
    const float* g2   = (const float*)d_in[22];
    const float* be2  = (const float*)d_in[23];
    const float* m2   = (const float*)d_in[24];
    const float* v2   = (const float*)d_in[25];
    float* out = (float*)d_out;

    float *H, *H2, *XL, *XR, *P;
    cudaGetSymbolAddress((void**)&H,  g_H);
    cudaGetSymbolAddress((void**)&H2, g_H2);
    cudaGetSymbolAddress((void**)&XL, g_XL);
    cudaGetSymbolAddress((void**)&XR, g_XR);
    cudaGetSymbolAddress((void**)&P,  g_pool);

    cudaFuncSetAttribute(gat_kernel, cudaFuncAttributeMaxDynamicSharedMemorySize, GAT_SMEM);

    const int M = BB * NN;  // 16384
    const int* src = ei;
    const int* dst = ei + EE;

    sort_p1<<<CHUNKS, CHSZ>>>(dst);
    sort_p2<<<1, 256>>>();
    sort_p3<<<CHUNKS, CHSZ>>>(src, dst);

    // node_proj
    gemm_tc<1><<<dim3(M / 128, HIDD / 128, 1), 256>>>(
        x, W1, W1, b1, b1, g1, be1, m1, v1, H, H, M, HIDD, FIN);

    // layer 0: XL and XR in one launch (grid.z selects)
    gemm_tc<0><<<dim3(M / 128, HIDD / 128, 2), 256>>>(
        H, Wl0, Wr0, bl0, br0, 0, 0, 0, 0, XL, XR, M, HIDD, HIDD);
    gat_kernel<<<dim3(BB, HH), 256, GAT_SMEM>>>(XL, XR, att0, bo0, H2);

    // layer 1
    gemm_tc<0><<<dim3(M / 128, HIDD / 128, 2), 256>>>(
        H2, Wl1, Wr1, bl1, br1, 0, 0, 0, 0, XL, XR, M, HIDD, HIDD);
    gat_kernel<<<dim3(BB, HH), 256, GAT_SMEM>>>(XL, XR, att1, bo1, H);

    // pool + output proj
    pool_kernel<<<BB, HIDD>>>(H, P);
    gemm2_kernel<<<BB, HIDD>>>(P, W2, b2, g2, be2, m2, v2, out);
}

// round 14
// speedup vs baseline: 1.1547x; 1.0718x over previous
#include <cuda_runtime.h>
#include <cuda_fp16.h>
#include <math.h>

#define BB   64
#define NN   256
#define HIDD 256
#define HH   4
#define CC   64
#define EE   8192
#define FIN  768
#define CHUNKS 32
#define CHSZ   256         // EE / CHUNKS
#define TWW    640         // per-warp scratch floats: 32 edges * stride 20

typedef unsigned long long ull;

// ---------------- scratch (no allocations allowed) ----------------
__device__ float g_H [(size_t)BB * NN * HIDD];
__device__ float g_H2[(size_t)BB * NN * HIDD];
__device__ float g_XL[(size_t)BB * NN * HIDD];
__device__ float g_XR[(size_t)BB * NN * HIDD];
__device__ float g_pool[BB * HIDD];
__device__ __half g_Wt[458752];        // transposed half weights: W1t|Wl0t|Wr0t|Wl1t|Wr1t
__device__ int   g_srcs[EE];
__device__ int   g_off[NN + 1];
__device__ int   g_cnt [CHUNKS][NN];
__device__ int   g_base[CHUNKS][NN];
__device__ int   g_rank[EE];

__device__ __forceinline__ float gelu_f(float x) {
    return 0.5f * x * (1.0f + erff(x * 0.70710678118654752f));
}

__device__ __forceinline__ unsigned packh2(float x, float y) {
    __half2 h = __floats2half2_rn(x, y);
    return *(unsigned*)&h;
}

__device__ __forceinline__ void mma16(float& c0, float& c1, float& c2, float& c3,
                                      unsigned a0, unsigned a1, unsigned a2, unsigned a3,
                                      unsigned b0, unsigned b1) {
    asm volatile(
        "mma.sync.aligned.m16n8k16.row.col.f32.f16.f16.f32 "
        "{%0,%1,%2,%3},{%4,%5,%6,%7},{%8,%9},{%0,%1,%2,%3};"
        : "+f"(c0), "+f"(c1), "+f"(c2), "+f"(c3)
        : "r"(a0), "r"(a1), "r"(a2), "r"(a3), "r"(b0), "r"(b1));
}

// ---- packed f32x2 helpers (sm_103a) ----
__device__ __forceinline__ ull add2_(ull a, ull b) {
    ull d; asm("add.rn.f32x2 %0,%1,%2;" : "=l"(d) : "l"(a), "l"(b)); return d;
}
__device__ __forceinline__ ull mul2_(ull a, ull b) {
    ull d; asm("mul.rn.f32x2 %0,%1,%2;" : "=l"(d) : "l"(a), "l"(b)); return d;
}
__device__ __forceinline__ ull fma2_(ull a, ull b, ull c) {
    ull d; asm("fma.rn.f32x2 %0,%1,%2,%3;" : "=l"(d) : "l"(a), "l"(b), "l"(c)); return d;
}
__device__ __forceinline__ ull pk2(float x) {
    ull d; unsigned u = __float_as_uint(x);
    asm("mov.b64 %0,{%1,%1};" : "=l"(d) : "r"(u)); return d;
}
__device__ __forceinline__ ull pk2two(float x, float y) {
    ull d;
    asm("mov.b64 %0,{%1,%2};" : "=l"(d) : "r"(__float_as_uint(x)), "r"(__float_as_uint(y)));
    return d;
}
__device__ __forceinline__ float2 unpk(ull v) {
    unsigned lo, hi;
    asm("mov.b64 {%0,%1},%2;" : "=r"(lo), "=r"(hi) : "l"(v));
    return make_float2(__uint_as_float(lo), __uint_as_float(hi));
}

#define CFENCE() asm volatile("" ::: "memory")

// ---------------- weight transpose + fp16 convert (once per launch) ----------------
// Wt[n][k] = half(W[k][n]).  W1: 768x256 (192 tiles); others 256x256 (64 tiles each).
__global__ void prep_w(const float* __restrict__ W1,
                       const float* __restrict__ Wl0, const float* __restrict__ Wr0,
                       const float* __restrict__ Wl1, const float* __restrict__ Wr1) {
    __shared__ float s[32][33];
    int bid = blockIdx.x;
    const float* W; __half* T; int K, N, tk, tn;
    if (bid < 192) {
        W = W1; T = g_Wt; K = 768; N = 256; tk = bid >> 3; tn = bid & 7;
    } else {
        int r = (bid - 192) >> 6, t = (bid - 192) & 63;
        K = 256; N = 256; tk = t >> 3; tn = t & 7;
        W = (r == 0) ? Wl0 : (r == 1) ? Wr0 : (r == 2) ? Wl1 : Wr1;
        T = g_Wt + 196608 + r * 65536;
    }
    int tx = threadIdx.x, ty = threadIdx.y;   // 32 x 8
    #pragma unroll
    for (int i = 0; i < 4; i++)
        s[ty + 8 * i][tx] = W[(size_t)(tk * 32 + ty + 8 * i) * N + tn * 32 + tx];
    __syncthreads();
    #pragma unroll
    for (int i = 0; i < 4; i++)
        T[(size_t)(tn * 32 + ty + 8 * i) * K + tk * 32 + tx] = __float2half(s[tx][ty + 8 * i]);
}

// ---------------- parallel deterministic counting sort, 3 phases ----------------
__global__ void sort_p1(const int* __restrict__ dst) {
    __shared__ int sd[CHSZ];
    const int ch = blockIdx.x, e = threadIdx.x;
    const int d = dst[ch * CHSZ + e];
    sd[e] = d;
    g_cnt[ch][e] = 0;
    __syncthreads();
    int rank = 0, tot = 0;
    #pragma unroll 8
    for (int j = 0; j < CHSZ; j++) {
        int v = sd[j];
        int m = (v == d);
        tot += m;
        rank += m & (j < e);
    }
    g_rank[ch * CHSZ + e] = rank;
    if (rank == 0) g_cnt[ch][d] = tot;
}

__global__ void sort_p2() {
    __shared__ int wsum[8];
    const int t = threadIdx.x;
    int run = 0;
    #pragma unroll
    for (int c = 0; c < CHUNKS; c++) {
        g_base[c][t] = run;
        run += g_cnt[c][t];
    }
    const int lane = t & 31, w = t >> 5;
    int inc = run;
    #pragma unroll
    for (int o = 1; o < 32; o <<= 1) {
        int n = __shfl_up_sync(0xffffffffu, inc, o);
        if (lane >= o) inc += n;
    }
    if (lane == 31) wsum[w] = inc;
    __syncthreads();
    if (t == 0) {
        int r = 0;
        #pragma unroll
        for (int i = 0; i < 8; i++) { int v = wsum[i]; wsum[i] = r; r += v; }
    }
    __syncthreads();
    const int offset = inc + wsum[w] - run;
    #pragma unroll
    for (int c = 0; c < CHUNKS; c++) g_base[c][t] += offset;
    g_off[t] = offset;
    if (t == NN - 1) g_off[NN] = EE;
}

__global__ void sort_p3(const int* __restrict__ src, const int* __restrict__ dst) {
    const int e = blockIdx.x * CHSZ + threadIdx.x;
    const int d = dst[e];
    g_srcs[g_base[blockIdx.x][d] + g_rank[e]] = src[e];
}

// ---------------- fp16 tensor-core GEMM: 128x128 CTA tile, BK=16 ----------------
// A: fp32, converted to half at staging. B: pre-transposed half Wt[n][k].
// As/Bs rows of 12 uints (8 used + 4 pad) -> frag LDS.32 conflict-free (12g mod 32 distinct).
template <int MODE>
__global__ void __launch_bounds__(256)
gemm_fp16(const float* __restrict__ A,
          const __half* __restrict__ B0t, const __half* __restrict__ B1t,
          const float* __restrict__ bias0, const float* __restrict__ bias1,
          const float* __restrict__ gam, const float* __restrict__ bet,
          const float* __restrict__ rm, const float* __restrict__ rv,
          float* __restrict__ C0, float* __restrict__ C1,
          int M, int Nn, int K) {
    __shared__ unsigned As[2][128 * 12];
    __shared__ unsigned Bs[2][128 * 12];

    const __half* Bt  = blockIdx.z ? B1t : B0t;
    const float* bias = blockIdx.z ? bias1 : bias0;
    float* C          = blockIdx.z ? C1 : C0;

    const int tid = threadIdx.x;
    const int lane = tid & 31, wid = tid >> 5;
    const int gid = lane >> 2, tig = lane & 3;
    const int wm = wid & 1;     // 2 x 64 rows
    const int wn = wid >> 1;    // 4 x 32 cols
    const int bm = blockIdx.x * 128;
    const int bn = blockIdx.y * 128;

    // A staging: 128 rows x 16 fp32 = 512 float4 -> 2/thread
    const int ar0 = tid >> 2, ac0 = (tid & 3) << 2;
    const int ar1 = ar0 + 64;
    // B staging: 128 cols x 16 halves (32B) -> 256 uint4 -> 1/thread
    const int bcol = tid >> 1, bhalf = tid & 1;

    const float* Ap0 = A + (size_t)(bm + ar0) * K + ac0;
    const float* Ap1 = A + (size_t)(bm + ar1) * K + ac0;
    const __half* Bp = Bt + (size_t)(bn + bcol) * K + bhalf * 8;

    float acc[4][4][4];
    #pragma unroll
    for (int i = 0; i < 4; i++)
        #pragma unroll
        for (int j = 0; j < 4; j++)
            #pragma unroll
            for (int q = 0; q < 4; q++) acc[i][j][q] = 0.f;

    float4 pa0 = *(const float4*)Ap0;
    float4 pa1 = *(const float4*)Ap1;
    uint4  pb  = *(const uint4*)Bp;

    {
        uint2 u;
        u.x = packh2(pa0.x, pa0.y); u.y = packh2(pa0.z, pa0.w);
        *(uint2*)&As[0][ar0 * 12 + (ac0 >> 1)] = u;
        u.x = packh2(pa1.x, pa1.y); u.y = packh2(pa1.z, pa1.w);
        *(uint2*)&As[0][ar1 * 12 + (ac0 >> 1)] = u;
        *(uint4*)&Bs[0][bcol * 12 + bhalf * 4] = pb;
    }
    __syncthreads();

    const int nsteps = K >> 4;
    int cur = 0;
    for (int kt = 0; kt < nsteps; kt++) {
        if (kt + 1 < nsteps) {
            pa0 = *(const float4*)(Ap0 + (kt + 1) * 16);
            pa1 = *(const float4*)(Ap1 + (kt + 1) * 16);
            pb  = *(const uint4*)(Bp + (kt + 1) * 16);
        }
        // fragments (one K=16 mma step per kt)
        unsigned af[4][4], bf[4][2];
        #pragma unroll
        for (int mt = 0; mt < 4; mt++) {
            int r = wm * 64 + mt * 16 + gid;
            af[mt][0] = As[cur][r * 12 + tig];
            af[mt][1] = As[cur][(r + 8) * 12 + tig];
            af[mt][2] = As[cur][r * 12 + tig + 4];
            af[mt][3] = As[cur][(r + 8) * 12 + tig + 4];
        }
        #pragma unroll
        for (int nt = 0; nt < 4; nt++) {
            int col = wn * 32 + nt * 8 + gid;
            bf[nt][0] = Bs[cur][col * 12 + tig];
            bf[nt][1] = Bs[cur][col * 12 + tig + 4];
        }
        #pragma unroll
        for (int mt = 0; mt < 4; mt++)
            #pragma unroll
            for (int nt = 0; nt < 4; nt++)
                mma16(acc[mt][nt][0], acc[mt][nt][1], acc[mt][nt][2], acc[mt][nt][3],
                      af[mt][0], af[mt][1], af[mt][2], af[mt][3],
                      bf[nt][0], bf[nt][1]);
        if (kt + 1 < nsteps) {
            int nxt = cur ^ 1;
            uint2 u;
            u.x = packh2(pa0.x, pa0.y); u.y = packh2(pa0.z, pa0.w);
            *(uint2*)&As[nxt][ar0 * 12 + (ac0 >> 1)] = u;
            u.x = packh2(pa1.x, pa1.y); u.y = packh2(pa1.z, pa1.w);
            *(uint2*)&As[nxt][ar1 * 12 + (ac0 >> 1)] = u;
            *(uint4*)&Bs[nxt][bcol * 12 + bhalf * 4] = pb;
            __syncthreads();
            cur = nxt;
        }
    }

    #pragma unroll
    for (int nt = 0; nt < 4; nt++) {
        int col = bn + wn * 32 + nt * 8 + 2 * tig;
        float bi0 = bias[col], bi1 = bias[col + 1];
        float g0 = 1.f, g1 = 1.f, b0 = 0.f, b1 = 0.f, m0 = 0.f, m1 = 0.f, s0 = 1.f, s1 = 1.f;
        if (MODE == 1) {
            g0 = gam[col]; g1 = gam[col + 1];
            b0 = bet[col]; b1 = bet[col + 1];
            m0 = rm[col];  m1 = rm[col + 1];
            s0 = rsqrtf(rv[col] + 1e-5f);
            s1 = rsqrtf(rv[col + 1] + 1e-5f);
        }
        #pragma unroll
        for (int mt = 0; mt < 4; mt++) {
            int row0 = bm + wm * 64 + mt * 16 + gid;
            float t0 = acc[mt][nt][0] + bi0;
            float t1 = acc[mt][nt][1] + bi1;
            float t2 = acc[mt][nt][2] + bi0;
            float t3 = acc[mt][nt][3] + bi1;
            if (MODE == 1) {
                t0 = gelu_f((t0 - m0) * s0 * g0 + b0);
                t1 = gelu_f((t1 - m1) * s1 * g1 + b1);
                t2 = gelu_f((t2 - m0) * s0 * g0 + b0);
                t3 = gelu_f((t3 - m1) * s1 * g1 + b1);
            }
            float2 o0 = {t0, t1};
            float2 o1 = {t2, t3};
            *(float2*)(C + (size_t)row0 * Nn + col) = o0;
            *(float2*)(C + (size_t)(row0 + 8) * Nn + col) = o1;
        }
    }
}

// ---------------- GATv2 v10 (unchanged from R13 champion) ----------------
__global__ void __launch_bounds__(256, 2)
gat_kernel(const float* __restrict__ XL, const float* __restrict__ XR,
           const float* __restrict__ att, const float* __restrict__ bo,
           float* __restrict__ OUT) {
    extern __shared__ float sm[];
    float* sxl = sm;                        // NN * 64  (64 KB)
    float* stw = sm + NN * 64;              // 8 * TWW  (20 KB)

    const int b = blockIdx.x, h = blockIdx.y;
    const int tid = threadIdx.x;
    const int w = tid >> 5, lane = tid & 31;
    const int p = lane >> 4, q = lane & 15;

    const float* xlb = XL + (size_t)b * NN * HIDD + h * CC;
    for (int i = tid; i < NN * 16; i += 256) {
        int n = i >> 4, g = i & 15;
        *(float4*)&sxl[n * 64 + g * 4] = *(const float4*)(xlb + (size_t)n * HIDD + g * 4);
    }
    __syncthreads();

    const float4 av = *(const float4*)(att + h * CC + 4 * q);
    const ull c6a = pk2two(0.6f * av.x, 0.6f * av.y);
    const ull c6b = pk2two(0.6f * av.z, 0.6f * av.w);
    const ull c4a = pk2two(0.4f * av.x, 0.4f * av.y);
    const ull c4b = pk2two(0.4f * av.z, 0.4f * av.w);
    const float4 bo4 = *(const float4*)(bo + h * CC + 4 * q);
    const ull ABSM = 0x7fffffff7fffffffULL;

    float* tw = stw + w * TWW;
    const int* __restrict__ srcs = g_srcs;
    const float* xr_base = XR + (size_t)b * NN * HIDD + h * CC + 4 * q;

    for (int d = w; d < NN; d += 8) {
        const int e0 = g_off[d], e1 = g_off[d + 1];
        const float4 xr4 = *(const float4*)(xr_base + (size_t)d * HIDD);
        const ull xra = pk2two(xr4.x, xr4.y);
        const ull xrb = pk2two(xr4.z, xr4.w);

        float S = 0.f;
        ull acc0 = 0ull, acc1 = 0ull;

        for (int base = e0; base < e1; base += 32) {
            const int n = min(32, e1 - base);
            const int sreg = srcs[min(base + lane, EE - 1)];
            ulonglong2 vreg[16];

            CFENCE();
            #pragma unroll
            for (int k = 0; k < 16; k++) {
                int s = __shfl_sync(0xffffffffu, sreg, 2 * k + p);
                ulonglong2 rv = *(const ulonglong2*)(sxl + (s << 6) + 4 * q);
                vreg[k] = rv;
                ull t0 = add2_(rv.x, xra);
                ull t1 = add2_(rv.y, xrb);
                ull m = fma2_(t0 & ABSM, c4a, mul2_(t0, c6a));
                m = fma2_(t1 & ABSM, c4b, fma2_(t1, c6b, m));
                float2 pr = unpk(m);
                tw[(2 * k + p) * 20 + q] = pr.x + pr.y;
            }
            CFENCE();

            float wgt = 0.f;
            {
                const float4* r4 = (const float4*)(tw + lane * 20);
                float4 q0 = r4[0], q1 = r4[1], q2 = r4[2], q3 = r4[3];
                float s0 = ((q0.x + q0.y) + (q0.z + q0.w)) + ((q1.x + q1.y) + (q1.z + q1.w));
                float s1 = ((q2.x + q2.y) + (q2.z + q2.w)) + ((q3.x + q3.y) + (q3.z + q3.w));
                if (lane < n) wgt = __expf(s0 + s1);
            }
            float ss = wgt;
            #pragma unroll
            for (int o = 16; o > 0; o >>= 1) ss += __shfl_xor_sync(0xffffffffu, ss, o);
            S += ss;

            #pragma unroll
            for (int k = 0; k < 16; k++) {
                float wj = __shfl_sync(0xffffffffu, wgt, 2 * k + p);
                ull wv = pk2(wj);
                acc0 = fma2_(vreg[k].x, wv, acc0);
                acc1 = fma2_(vreg[k].y, wv, acc1);
            }
        }

        float2 a0 = unpk(acc0), a1 = unpk(acc1);
        a0.x += __shfl_xor_sync(0xffffffffu, a0.x, 16);
        a0.y += __shfl_xor_sync(0xffffffffu, a0.y, 16);
        a1.x += __shfl_xor_sync(0xffffffffu, a1.x, 16);
        a1.y += __shfl_xor_sync(0xffffffffu, a1.y, 16);

        const float inv = 1.f / (S + 1e-16f);
        float4 ov;
        ov.x = gelu_f(fmaf(a0.x, inv, bo4.x));
        ov.y = gelu_f(fmaf(a0.y, inv, bo4.y));
        ov.z = gelu_f(fmaf(a1.x, inv, bo4.z));
        ov.w = gelu_f(fmaf(a1.y, inv, bo4.w));
        if (p == 0)
            *(float4*)(OUT + ((size_t)b * NN + d) * HIDD + h * CC + 4 * q) = ov;
    }
}

// ---------------- mean-pool over nodes ----------------
__global__ void pool_kernel(const float* __restrict__ H, float* __restrict__ P) {
    int b = blockIdx.x, f = threadIdx.x;
    float s = 0.f;
    #pragma unroll 4
    for (int n = 0; n < NN; n++) s += H[((size_t)b * NN + n) * HIDD + f];
    P[b * HIDD + f] = s * (1.0f / NN);
}

// ---------------- tiny output GEMM + BN + GELU ----------------
__global__ void gemm2_kernel(const float* __restrict__ P, const float* __restrict__ W,
                             const float* __restrict__ bias,
                             const float* __restrict__ gam, const float* __restrict__ bet,
                             const float* __restrict__ rm, const float* __restrict__ rv,
                             float* __restrict__ out) {
    __shared__ float sp[HIDD];
    int b = blockIdx.x, j = threadIdx.x;
    sp[j] = P[b * HIDD + j];
    __syncthreads();
    float acc = 0.f;
    #pragma unroll 4
    for (int k = 0; k < HIDD; k++) acc = fmaf(sp[k], W[(size_t)k * HIDD + j], acc);
    float t = acc + bias[j];
    t = (t - rm[j]) * rsqrtf(rv[j] + 1e-5f) * gam[j] + bet[j];
    out[b * HIDD + j] = gelu_f(t);
}

#define GAT_SMEM ((NN * 64 + 8 * TWW) * (int)sizeof(float))

extern "C" void kernel_launch(void* const* d_in, const int* in_sizes, int n_in,
                              void* d_out, int out_size) {
    const float* x    = (const float*)d_in[0];
    const int*   ei   = (const int*)d_in[1];
    const float* W1   = (const float*)d_in[2];
    const float* b1   = (const float*)d_in[3];
    const float* g1   = (const float*)d_in[4];
    const float* be1  = (const float*)d_in[5];
    const float* m1   = (const float*)d_in[6];
    const float* v1   = (const float*)d_in[7];
    const float* Wl0  = (const float*)d_in[8];
    const float* bl0  = (const float*)d_in[9];
    const float* Wr0  = (const float*)d_in[10];
    const float* br0  = (const float*)d_in[11];
    const float* att0 = (const float*)d_in[12];
    const float* bo0  = (const float*)d_in[13];
    const float* Wl1  = (const float*)d_in[14];
    const float* bl1  = (const float*)d_in[15];
    const float* Wr1  = (const float*)d_in[16];
    const float* br1  = (const float*)d_in[17];
    const float* att1 = (const float*)d_in[18];
    const float* bo1  = (const float*)d_in[19];
    const float* W2   = (const float*)d_in[20];
    const float* b2   = (const float*)d_in[21];
    const float* g2   = (const float*)d_in[22];
    const float* be2  = (const float*)d_in[23];
    const float* m2   = (const float*)d_in[24];
    const float* v2   = (const float*)d_in[25];
    float* out = (float*)d_out;

    float *H, *H2, *XL, *XR, *P;
    __half* Wt;
    cudaGetSymbolAddress((void**)&H,  g_H);
    cudaGetSymbolAddress((void**)&H2, g_H2);
    cudaGetSymbolAddress((void**)&XL, g_XL);
    cudaGetSymbolAddress((void**)&XR, g_XR);
    cudaGetSymbolAddress((void**)&P,  g_pool);
    cudaGetSymbolAddress((void**)&Wt, g_Wt);

    const __half* W1t  = Wt;                  // [256][768]
    const __half* Wl0t = Wt + 196608;         // [256][256]
    const __half* Wr0t = Wt + 262144;
    const __half* Wl1t = Wt + 327680;
    const __half* Wr1t = Wt + 393216;

    cudaFuncSetAttribute(gat_kernel, cudaFuncAttributeMaxDynamicSharedMemorySize, GAT_SMEM);

    const int M = BB * NN;  // 16384
    const int* src = ei;
    const int* dst = ei + EE;

    prep_w<<<448, dim3(32, 8)>>>(W1, Wl0, Wr0, Wl1, Wr1);
    sort_p1<<<CHUNKS, CHSZ>>>(dst);
    sort_p2<<<1, 256>>>();
    sort_p3<<<CHUNKS, CHSZ>>>(src, dst);

    // node_proj (fp16 tensor cores, K=768)
    gemm_fp16<1><<<dim3(M / 128, HIDD / 128, 1), 256>>>(
        x, W1t, W1t, b1, b1, g1, be1, m1, v1, H, H, M, HIDD, FIN);

    // layer 0: XL and XR in one launch (grid.z selects)
    gemm_fp16<0><<<dim3(M / 128, HIDD / 128, 2), 256>>>(
        H, Wl0t, Wr0t, bl0, br0, 0, 0, 0, 0, XL, XR, M, HIDD, HIDD);
    gat_kernel<<<dim3(BB, HH), 256, GAT_SMEM>>>(XL, XR, att0, bo0, H2);

    // layer 1
    gemm_fp16<0><<<dim3(M / 128, HIDD / 128, 2), 256>>>(
        H2, Wl1t, Wr1t, bl1, br1, 0, 0, 0, 0, XL, XR, M, HIDD, HIDD);
    gat_kernel<<<dim3(BB, HH), 256, GAT_SMEM>>>(XL, XR, att1, bo1, H);

    // pool + output proj
    pool_kernel<<<BB, HIDD>>>(H, P);
    gemm2_kernel<<<BB, HIDD>>>(P, W2, b2, g2, be2, m2, v2, out);
}